// round 7
// baseline (speedup 1.0000x reference)
#include <cuda_runtime.h>
#include <math.h>

#define NB 64
#define NA 8732
#define NA4 2183            // NA/4 exact
#define NG 50
#define NC 21
#define NBX 18              // ceil(NA/512)
#define HC 4                // histogram copies
#define IOU_THR 0.5f
#define VXY 0.1f
#define VWH 0.2f
#define EPS16 9.765625e-4

// ---------------- device scratch ----------------
__device__ float  g_lossneg[NB * NA];
__device__ float  g_psl1[NB * NBX];
__device__ float  g_pce [NB * NBX];
__device__ int    g_pnp [NB * NBX];
__device__ double g_ob_cp[NB];
__device__ double g_ob_cn[NB];
__device__ double g_ob_np[NB];
__device__ double g_ob_sl[NB];
__device__ int    g_ctr;

// ---------------- helpers ----------------
__device__ __forceinline__ double warpRedD(double v) {
    #pragma unroll
    for (int o = 16; o > 0; o >>= 1) v += __shfl_down_sync(0xFFFFFFFFu, v, o);
    return v;
}
__device__ __forceinline__ float warpRedF(float v) {
    #pragma unroll
    for (int o = 16; o > 0; o >>= 1) v += __shfl_down_sync(0xFFFFFFFFu, v, o);
    return v;
}
__device__ __forceinline__ float smoothL1(float d) {
    float ad = fabsf(d);
    return ad < 1.0f ? 0.5f * d * d : ad - 0.5f;
}
__device__ __forceinline__ unsigned ordkey(float f) {
    unsigned u = __float_as_uint(f);
    return u ^ ((u >> 31) ? 0xFFFFFFFFu : 0x80000000u);
}
__device__ __forceinline__ float ordval(unsigned k) {
    unsigned u = (k & 0x80000000u) ? (k ^ 0x80000000u) : ~k;
    return __uint_as_float(u);
}
__device__ __forceinline__ unsigned warpSufIncl(unsigned v, int lane) {
    #pragma unroll
    for (int d = 1; d < 32; d <<= 1) {
        unsigned t = __shfl_down_sync(0xFFFFFFFFu, v, d);
        if (lane + d < 32) v += t;
    }
    return v;
}

// ---------------- kernel 1: match + box loss + CE (2 anchors/thread) ----------------
__global__ __launch_bounds__(256) void k_match(const float* __restrict__ preg,
                        const float* __restrict__ pcls,
                        const float* __restrict__ ancs,
                        const float* __restrict__ gbox,
                        const int*   __restrict__ glab) {
    const int b = blockIdx.y;
    const int tid = threadIdx.x;
    const int a0 = blockIdx.x * 512 + tid;
    const int a1 = a0 + 256;

    __shared__ float4 s_gb[NG];
    __shared__ float  s_ga[NG];
    __shared__ int    s_gl[NG];
    if (tid < NG) {
        float4 gb = reinterpret_cast<const float4*>(gbox)[b * NG + tid];
        int    gl = glab[b * NG + tid];
        float  ag = (gb.z - gb.x) * (gb.w - gb.y);
        if (gl <= 0) { gb = make_float4(0.f, 0.f, 0.f, 0.f); ag = 0.f; }
        s_gb[tid] = gb;
        s_ga[tid] = ag;
        s_gl[tid] = gl;
    }
    __syncthreads();

    float sl1_c = 0.f, ce_c = 0.f;
    int pos_c = 0;

    const bool v0 = (a0 < NA), v1 = (a1 < NA);

    float4 anc0 = make_float4(0.5f, 0.5f, 1.f, 1.f), anc1 = anc0;
    if (v0) anc0 = reinterpret_cast<const float4*>(ancs)[a0];
    if (v1) anc1 = reinterpret_cast<const float4*>(ancs)[a1];

    float al0 = anc0.x - anc0.z * 0.5f, at0 = anc0.y - anc0.w * 0.5f;
    float ar0 = anc0.x + anc0.z * 0.5f, ab0 = anc0.y + anc0.w * 0.5f;
    float area0 = (ar0 - al0) * (ab0 - at0);
    float al1 = anc1.x - anc1.z * 0.5f, at1 = anc1.y - anc1.w * 0.5f;
    float ar1 = anc1.x + anc1.z * 0.5f, ab1 = anc1.y + anc1.w * 0.5f;
    float area1 = (ar1 - al1) * (ab1 - at1);

    float inb0 = -1.f, unb0 = 1.f, inb1 = -1.f, unb1 = 1.f;
    int bi0 = 0, bi1 = 0;
    #pragma unroll
    for (int g = 0; g < NG; g++) {
        float4 gb = s_gb[g];
        float ga = s_ga[g];
        // anchor 0
        {
            float ltx = fmaxf(gb.x, al0), lty = fmaxf(gb.y, at0);
            float rbx = fminf(gb.z, ar0), rby = fminf(gb.w, ab0);
            float w = fmaxf(rbx - ltx, 0.0f), h = fmaxf(rby - lty, 0.0f);
            float inter = w * h;
            float uni = ga + area0 - inter;
            if (inter * unb0 > inb0 * uni) { inb0 = inter; unb0 = uni; bi0 = g; }
        }
        // anchor 1
        {
            float ltx = fmaxf(gb.x, al1), lty = fmaxf(gb.y, at1);
            float rbx = fminf(gb.z, ar1), rby = fminf(gb.w, ab1);
            float w = fmaxf(rbx - ltx, 0.0f), h = fmaxf(rby - lty, 0.0f);
            float inter = w * h;
            float uni = ga + area1 - inter;
            if (inter * unb1 > inb1 * uni) { inb1 = inter; unb1 = uni; bi1 = g; }
        }
    }
    bool pos0 = (2.0f * inb0 >= unb0);
    bool pos1 = (2.0f * inb1 >= unb1);

    const float* pregb = preg + (size_t)b * 4 * NA;
    const float* pclsb = pcls + (size_t)b * NC * NA;

    // ---- anchor 0 ----
    if (v0) {
        float4 gb = s_gb[bi0];
        float gcx = (gb.x + gb.z) * 0.5f, gcy = (gb.y + gb.w) * 0.5f;
        float gw = gb.z - gb.x, gh = gb.w - gb.y;
        float tx = (gcx - anc0.x) / (anc0.z * VXY);
        float ty = (gcy - anc0.y) / (anc0.w * VXY);
        float tw = __logf(fmaxf(gw, 1e-6f) / anc0.z) * (1.0f / VWH);
        float th = __logf(fmaxf(gh, 1e-6f) / anc0.w) * (1.0f / VWH);
        float d0 = pregb[0 * NA + a0] - tx;
        float d1 = pregb[1 * NA + a0] - ty;
        float d2 = pregb[2 * NA + a0] - tw;
        float d3 = pregb[3 * NA + a0] - th;
        float sl1 = smoothL1(d0) + smoothL1(d1) + smoothL1(d2) + smoothL1(d3);

        const float* pc = pclsb + a0;
        float s = 0.0f;
        #pragma unroll
        for (int c = 0; c < NC; c++) s += __expf(pc[c * NA]);
        float lse = __logf(s);
        int lab = pos0 ? s_gl[bi0] : 0;
        float ce = lse - pc[lab * NA];

        g_lossneg[b * NA + a0] = pos0 ? -1.0f : ce;
        if (pos0) { pos_c++; ce_c += ce; sl1_c += sl1; }
    }
    // ---- anchor 1 ----
    if (v1) {
        float4 gb = s_gb[bi1];
        float gcx = (gb.x + gb.z) * 0.5f, gcy = (gb.y + gb.w) * 0.5f;
        float gw = gb.z - gb.x, gh = gb.w - gb.y;
        float tx = (gcx - anc1.x) / (anc1.z * VXY);
        float ty = (gcy - anc1.y) / (anc1.w * VXY);
        float tw = __logf(fmaxf(gw, 1e-6f) / anc1.z) * (1.0f / VWH);
        float th = __logf(fmaxf(gh, 1e-6f) / anc1.w) * (1.0f / VWH);
        float d0 = pregb[0 * NA + a1] - tx;
        float d1 = pregb[1 * NA + a1] - ty;
        float d2 = pregb[2 * NA + a1] - tw;
        float d3 = pregb[3 * NA + a1] - th;
        float sl1 = smoothL1(d0) + smoothL1(d1) + smoothL1(d2) + smoothL1(d3);

        const float* pc = pclsb + a1;
        float s = 0.0f;
        #pragma unroll
        for (int c = 0; c < NC; c++) s += __expf(pc[c * NA]);
        float lse = __logf(s);
        int lab = pos1 ? s_gl[bi1] : 0;
        float ce = lse - pc[lab * NA];

        g_lossneg[b * NA + a1] = pos1 ? -1.0f : ce;
        if (pos1) { pos_c++; ce_c += ce; sl1_c += sl1; }
    }

    sl1_c = warpRedF(sl1_c);
    ce_c  = warpRedF(ce_c);
    float posf = warpRedF((float)pos_c);
    __shared__ float sh0[8], sh1[8], sh2[8];
    int wid = tid >> 5, lid = tid & 31;
    if (lid == 0) { sh0[wid] = sl1_c; sh1[wid] = ce_c; sh2[wid] = posf; }
    __syncthreads();
    if (wid == 0) {
        float x0 = (lid < 8) ? sh0[lid] : 0.f;
        float x1 = (lid < 8) ? sh1[lid] : 0.f;
        float x2 = (lid < 8) ? sh2[lid] : 0.f;
        x0 = warpRedF(x0); x1 = warpRedF(x1); x2 = warpRedF(x2);
        if (lid == 0) {
            int p = b * NBX + blockIdx.x;
            g_psl1[p] = x0;
            g_pce [p] = x1;
            g_pnp [p] = (int)(x2 + 0.5f);
        }
    }
}

// ---------------- kernel 2: register-resident radix top-K ----------------
// Keys: real negatives (ce>0) -> bins >= 1024; positives (-1.0) -> bin 515;
// invalid slots -> key 0 (bin 0). Since K <= numneg the selected bin is always
// >= 1024, so fakes/positives never affect selection or the above-pivot sum.
__global__ __launch_bounds__(1024) void k_select(float* __restrict__ out) {
    const int b = blockIdx.x;
    const int tid = threadIdx.x;
    const int lane = tid & 31;
    const int wid = tid >> 5;

    __shared__ unsigned s_hist[HC * 2048];
    __shared__ unsigned s_wsum[32], s_wsum2[32];
    __shared__ unsigned s_bin;
    __shared__ int s_remS;
    __shared__ double s_np, s_ce, s_sl;
    __shared__ int s_ticket;
    __shared__ double sd[32];

    unsigned* myh = &s_hist[(wid & (HC - 1)) * 2048];

    // zero hist copies; warp 31 reduces per-block partials concurrently
    {
        uint4* h4 = reinterpret_cast<uint4*>(s_hist);
        h4[tid] = make_uint4(0, 0, 0, 0);
        h4[tid + 1024] = make_uint4(0, 0, 0, 0);
    }
    if (wid == 31) {
        double np = 0.0, ce = 0.0, sl = 0.0;
        if (lane < NBX) {
            int p = b * NBX + lane;
            np = (double)g_pnp[p];
            ce = (double)g_pce[p];
            sl = (double)g_psl1[p];
        }
        np = warpRedD(np); ce = warpRedD(ce); sl = warpRedD(sl);
        if (lane == 0) { s_np = np; s_ce = ce; s_sl = sl; }
    }

    // register-resident keys: 3 float4 per thread
    const float4* base4 = reinterpret_cast<const float4*>(&g_lossneg[b * NA]);
    unsigned k[12];
    {
        float4 f = base4[tid];
        k[0] = ordkey(f.x); k[1] = ordkey(f.y); k[2] = ordkey(f.z); k[3] = ordkey(f.w);
        f = base4[tid + 1024];
        k[4] = ordkey(f.x); k[5] = ordkey(f.y); k[6] = ordkey(f.z); k[7] = ordkey(f.w);
        if (tid < NA4 - 2048) {
            f = base4[tid + 2048];
            k[8] = ordkey(f.x); k[9] = ordkey(f.y); k[10] = ordkey(f.z); k[11] = ordkey(f.w);
        } else {
            k[8] = k[9] = k[10] = k[11] = 0u;
        }
    }
    __syncthreads();

    int npos = (int)(s_np + 0.5);
    int numneg = NA - npos;
    int K = (npos > 0) ? min(3 * npos, numneg) : (numneg > 0 ? 1 : 0);

    double dsum = 0.0;
    double negsum = 0.0;

    if (K > 0) {
        unsigned rem = (unsigned)K;
        unsigned b1, b2, b3;

        // ===== round 1: bits [21,32) =====
        #pragma unroll
        for (int j = 0; j < 12; j++) atomicAdd(&myh[k[j] >> 21], 1u);
        __syncthreads();
        // select bin (2048 bins, 2 per thread, 4 copies)
        {
            int base = tid * 2;
            unsigned h0 = 0, h1 = 0;
            #pragma unroll
            for (int c = 0; c < HC; c++) { h0 += s_hist[c * 2048 + base]; h1 += s_hist[c * 2048 + base + 1]; }
            unsigned v = warpSufIncl(h0 + h1, lane);
            if (lane == 0) s_wsum[wid] = v;
            __syncthreads();
            if (tid < 32) s_wsum2[tid] = warpSufIncl(s_wsum[tid], tid);
            __syncthreads();
            unsigned wexcl = (wid < 31) ? s_wsum2[wid + 1] : 0u;
            unsigned suf0 = v + wexcl;
            unsigned nxt0 = suf0 - h0;
            if (nxt0 < rem && rem <= suf0) { s_bin = (unsigned)base; s_remS = (int)(rem - nxt0); }
            unsigned nxt1 = nxt0 - h1;
            if (nxt1 < rem && rem <= nxt0) { s_bin = (unsigned)(base + 1); s_remS = (int)(rem - nxt1); }
            __syncthreads();
        }
        b1 = s_bin; rem = (unsigned)s_remS;
        #pragma unroll
        for (int j = 0; j < 12; j++) if ((k[j] >> 21) > b1) dsum += (double)ordval(k[j]);

        // ===== round 2: bits [10,21) =====
        {
            uint4* h4 = reinterpret_cast<uint4*>(s_hist);
            __syncthreads();
            h4[tid] = make_uint4(0, 0, 0, 0);
            h4[tid + 1024] = make_uint4(0, 0, 0, 0);
            __syncthreads();
        }
        #pragma unroll
        for (int j = 0; j < 12; j++)
            if ((k[j] >> 21) == b1) atomicAdd(&myh[(k[j] >> 10) & 2047u], 1u);
        __syncthreads();
        {
            int base = tid * 2;
            unsigned h0 = 0, h1 = 0;
            #pragma unroll
            for (int c = 0; c < HC; c++) { h0 += s_hist[c * 2048 + base]; h1 += s_hist[c * 2048 + base + 1]; }
            unsigned v = warpSufIncl(h0 + h1, lane);
            if (lane == 0) s_wsum[wid] = v;
            __syncthreads();
            if (tid < 32) s_wsum2[tid] = warpSufIncl(s_wsum[tid], tid);
            __syncthreads();
            unsigned wexcl = (wid < 31) ? s_wsum2[wid + 1] : 0u;
            unsigned suf0 = v + wexcl;
            unsigned nxt0 = suf0 - h0;
            if (nxt0 < rem && rem <= suf0) { s_bin = (unsigned)base; s_remS = (int)(rem - nxt0); }
            unsigned nxt1 = nxt0 - h1;
            if (nxt1 < rem && rem <= nxt0) { s_bin = (unsigned)(base + 1); s_remS = (int)(rem - nxt1); }
            __syncthreads();
        }
        b2 = s_bin; rem = (unsigned)s_remS;
        #pragma unroll
        for (int j = 0; j < 12; j++)
            if ((k[j] >> 21) == b1 && ((k[j] >> 10) & 2047u) > b2) dsum += (double)ordval(k[j]);

        // ===== round 3: bits [0,10) =====
        unsigned pref = (b1 << 21) | (b2 << 10);
        {
            uint4* h4 = reinterpret_cast<uint4*>(s_hist);
            __syncthreads();
            h4[tid] = make_uint4(0, 0, 0, 0);
            __syncthreads();
        }
        #pragma unroll
        for (int j = 0; j < 12; j++)
            if ((k[j] & 0xFFFFFC00u) == pref) atomicAdd(&myh[k[j] & 1023u], 1u);
        __syncthreads();
        {
            // 1024 bins, 1 per thread
            unsigned h0 = 0;
            #pragma unroll
            for (int c = 0; c < HC; c++) h0 += s_hist[c * 2048 + tid];
            unsigned v = warpSufIncl(h0, lane);
            if (lane == 0) s_wsum[wid] = v;
            __syncthreads();
            if (tid < 32) s_wsum2[tid] = warpSufIncl(s_wsum[tid], tid);
            __syncthreads();
            unsigned wexcl = (wid < 31) ? s_wsum2[wid + 1] : 0u;
            unsigned suf0 = v + wexcl;
            unsigned nxt0 = suf0 - h0;
            if (nxt0 < rem && rem <= suf0) { s_bin = (unsigned)tid; s_remS = (int)(rem - nxt0); }
            __syncthreads();
        }
        b3 = s_bin; rem = (unsigned)s_remS;
        #pragma unroll
        for (int j = 0; j < 12; j++)
            if ((k[j] & 0xFFFFFC00u) == pref && (k[j] & 1023u) > b3) dsum += (double)ordval(k[j]);

        unsigned pivot = pref | b3;
        float pv = ordval(pivot);

        double s = warpRedD(dsum);
        if (lane == 0) sd[wid] = s;
        __syncthreads();
        if (tid < 32) {
            double t = sd[tid];
            t = warpRedD(t);
            if (tid == 0) sd[0] = t + (double)rem * (double)pv;
        }
        __syncthreads();
        negsum = sd[0];
    }

    // publish per-batch results; last block combines
    if (tid == 0) {
        double nums = fmax(s_np, (double)EPS16);
        g_ob_cp[b] = s_ce / nums;
        g_ob_cn[b] = negsum / nums;
        g_ob_np[b] = s_np;
        g_ob_sl[b] = s_sl;
        __threadfence();
        s_ticket = atomicAdd(&g_ctr, 1);
    }
    __syncthreads();

    if (s_ticket == NB - 1) {
        double cp = 0.0, cn = 0.0, np = 0.0, sl = 0.0;
        if (tid < NB) {
            cp = g_ob_cp[tid]; cn = g_ob_cn[tid];
            np = g_ob_np[tid]; sl = g_ob_sl[tid];
        }
        cp = warpRedD(cp); cn = warpRedD(cn); np = warpRedD(np); sl = warpRedD(sl);
        __shared__ double f0[2], f1[2], f2[2], f3[2];
        if (lane == 0 && tid < NB) {
            f0[wid] = cp; f1[wid] = cn; f2[wid] = np; f3[wid] = sl;
        }
        __syncthreads();
        if (tid == 0) {
            double CP = f0[0] + f0[1];
            double CN = f1[0] + f1[1];
            double NP = f2[0] + f2[1];
            double SL = f3[0] + f3[1];
            double lbox = SL / fmax(NP, 1.0);
            out[0] = (float)(lbox + CP / (double)NB + CN / (double)NB);
            g_ctr = 0;
        }
    }
}

// ---------------- launch ----------------
extern "C" void kernel_launch(void* const* d_in, const int* in_sizes, int n_in,
                              void* d_out, int out_size) {
    const float* preg = (const float*)d_in[0];
    const float* pcls = (const float*)d_in[1];
    const float* ancs = (const float*)d_in[2];
    const float* gbox = (const float*)d_in[3];
    const int*   glab = (const int*)d_in[4];
    float* out = (float*)d_out;

    dim3 grid(NBX, NB);
    k_match<<<grid, 256>>>(preg, pcls, ancs, gbox, glab);
    k_select<<<NB, 1024>>>(out);
}